// round 3
// baseline (speedup 1.0000x reference)
#include <cuda_runtime.h>
#include <math.h>

#define Bsz 256
#define Tsz 256
#define Hsz 256
#define G3  768
#define BT0 32
#define ROWS0 48
#define ROWS1 24
#define STRIDE_H 260
#define STRIDE_X 516

__device__ float g_h1[(size_t)Bsz * Tsz * 2 * Hsz];   // layer-0 output [B][T][2H]
__device__ float g_hb0[2][2][Bsz * Hsz];              // layer-0 ping-pong per dir
__device__ float g_hb1[2][Bsz * Hsz];                 // layer-1 fwd ping-pong
__device__ float g_h2f[Bsz * Hsz];
__device__ float g_h2b[Bsz * Hsz];

typedef unsigned long long u64;

__device__ __forceinline__ u64 ffma2(u64 a, u64 b, u64 c) {
    u64 d;
    asm("fma.rn.f32x2 %0, %1, %2, %3;" : "=l"(d) : "l"(a), "l"(b), "l"(c));
    return d;
}
__device__ __forceinline__ float f2sum(u64 a) {
    return __uint_as_float((unsigned)(a & 0xffffffffull)) +
           __uint_as_float((unsigned)(a >> 32));
}
__device__ __forceinline__ float sigm(float v) { return 1.0f / (1.0f + expf(-v)); }

// --------------------------- layer 0 step ---------------------------------
// grid = (8 btiles, 16 jtiles, 2 dirs), block = 256
__global__ void __launch_bounds__(256, 2) gru_step0(
    const float* __restrict__ x,     // [B][T][4]
    const float* __restrict__ Wih0,  // [2][768][4]
    const float* __restrict__ Whh0,  // [2][768][256]
    const float* __restrict__ bih0,  // [2][768]
    const float* __restrict__ bhh0,  // [2][768]
    int s, int first)
{
    extern __shared__ float sm[];
    float* h_s = sm;                   // 32 x 260
    float* w_s = sm + BT0 * STRIDE_H;  // 48 x 260

    const int dir = blockIdx.z;
    const int t   = dir ? (Tsz - 1 - s) : s;
    const int btile = blockIdx.x, jtile = blockIdx.y, tid = threadIdx.x;
    const float* Whh = Whh0 + (size_t)dir * G3 * Hsz;

    for (int i = tid; i < ROWS0 * 64; i += 256) {
        int row = i >> 6, kk = (i & 63) << 2;
        int g = row >> 4, rj = row & 15;
        *(float4*)&w_s[row * STRIDE_H + kk] =
            *(const float4*)&Whh[(size_t)(g * Hsz + jtile * 16 + rj) * Hsz + kk];
    }
    const float* hprev = g_hb0[dir][s & 1];
    if (!first)
        for (int i = tid; i < BT0 * 64; i += 256) {
            int bl = i >> 6, kk = (i & 63) << 2;
            *(float4*)&h_s[bl * STRIDE_H + kk] =
                *(const float4*)&hprev[(btile * BT0 + bl) * Hsz + kk];
        }
    __syncthreads();

    const int tb = tid >> 3, tj = tid & 7;
    const int b = btile * BT0 + tb;

    float gh[3][2] = {};
    if (!first) {
        u64 acc[3][2] = {};
        const u64* hp = (const u64*)&h_s[tb * STRIDE_H];
        const u64* wp[3][2];
        #pragma unroll
        for (int g = 0; g < 3; g++)
            #pragma unroll
            for (int q = 0; q < 2; q++)
                wp[g][q] = (const u64*)&w_s[(g * 16 + q * 8 + tj) * STRIDE_H];
        #pragma unroll 4
        for (int k2 = 0; k2 < Hsz / 2; k2 += 2) {
            u64 h0 = hp[k2], h1 = hp[k2 + 1];
            #pragma unroll
            for (int g = 0; g < 3; g++)
                #pragma unroll
                for (int q = 0; q < 2; q++) {
                    acc[g][q] = ffma2(h0, wp[g][q][k2],     acc[g][q]);
                    acc[g][q] = ffma2(h1, wp[g][q][k2 + 1], acc[g][q]);
                }
        }
        #pragma unroll
        for (int g = 0; g < 3; g++)
            #pragma unroll
            for (int q = 0; q < 2; q++) gh[g][q] = f2sum(acc[g][q]);
    }

    const float4 xv = *(const float4*)&x[((size_t)b * Tsz + t) * 4];
    float* hnext = g_hb0[dir][(s & 1) ^ 1];

    #pragma unroll
    for (int q = 0; q < 2; q++) {
        int j = jtile * 16 + q * 8 + tj;
        const float4 wr = *(const float4*)&Wih0[((size_t)dir * G3 + 0 * Hsz + j) * 4];
        const float4 wz = *(const float4*)&Wih0[((size_t)dir * G3 + 1 * Hsz + j) * 4];
        const float4 wn = *(const float4*)&Wih0[((size_t)dir * G3 + 2 * Hsz + j) * 4];
        float xr = bih0[dir * G3 + 0 * Hsz + j] + xv.x * wr.x + xv.y * wr.y + xv.z * wr.z + xv.w * wr.w;
        float xz = bih0[dir * G3 + 1 * Hsz + j] + xv.x * wz.x + xv.y * wz.y + xv.z * wz.z + xv.w * wz.w;
        float xn = bih0[dir * G3 + 2 * Hsz + j] + xv.x * wn.x + xv.y * wn.y + xv.z * wn.z + xv.w * wn.w;

        float r = sigm(xr + gh[0][q] + bhh0[dir * G3 + 0 * Hsz + j]);
        float z = sigm(xz + gh[1][q] + bhh0[dir * G3 + 1 * Hsz + j]);
        float n = tanhf(xn + r * (gh[2][q] + bhh0[dir * G3 + 2 * Hsz + j]));
        float hpv = first ? 0.0f : h_s[tb * STRIDE_H + j];
        float hv = (1.0f - z) * n + z * hpv;

        hnext[b * Hsz + j] = hv;
        g_h1[((size_t)b * Tsz + t) * (2 * Hsz) + dir * Hsz + j] = hv;
    }
}

// --------------------------- layer 1 step ---------------------------------
// grid = (8 btiles, 32 jtiles), block = 256. bwd=1,first=1 -> single reverse step.
__global__ void __launch_bounds__(256, 1) gru_step1(
    const float* __restrict__ Wih1,  // [2][768][512]
    const float* __restrict__ Whh1,  // [2][768][256]
    const float* __restrict__ bih1,
    const float* __restrict__ bhh1,
    int t, int first, int bwd)
{
    extern __shared__ float sm[];
    float* h_s  = sm;                       // 32 x 260
    float* x_s  = sm + BT0 * STRIDE_H;      // 32 x 516
    float* w_s  = x_s + BT0 * STRIDE_X;     // 24 x 260
    float* wi_s = w_s + ROWS1 * STRIDE_H;   // 24 x 516

    const int btile = blockIdx.x, jtile = blockIdx.y, tid = threadIdx.x;
    const float* Wih = Wih1 + (size_t)bwd * G3 * (2 * Hsz);
    const float* Whh = Whh1 + (size_t)bwd * G3 * Hsz;
    const float* bih = bih1 + bwd * G3;
    const float* bhh = bhh1 + bwd * G3;

    for (int i = tid; i < ROWS1 * 64; i += 256) {
        int row = i >> 6, kk = (i & 63) << 2;
        int g = row >> 3, rj = row & 7;
        *(float4*)&w_s[row * STRIDE_H + kk] =
            *(const float4*)&Whh[(size_t)(g * Hsz + jtile * 8 + rj) * Hsz + kk];
    }
    for (int i = tid; i < ROWS1 * 128; i += 256) {
        int row = i >> 7, kk = (i & 127) << 2;
        int g = row >> 3, rj = row & 7;
        *(float4*)&wi_s[row * STRIDE_X + kk] =
            *(const float4*)&Wih[(size_t)(g * Hsz + jtile * 8 + rj) * (2 * Hsz) + kk];
    }
    for (int i = tid; i < BT0 * 128; i += 256) {
        int bl = i >> 7, kk = (i & 127) << 2;
        *(float4*)&x_s[bl * STRIDE_X + kk] =
            *(const float4*)&g_h1[((size_t)(btile * BT0 + bl) * Tsz + t) * (2 * Hsz) + kk];
    }
    const float* hprev = g_hb1[t & 1];
    if (!first)
        for (int i = tid; i < BT0 * 64; i += 256) {
            int bl = i >> 6, kk = (i & 63) << 2;
            *(float4*)&h_s[bl * STRIDE_H + kk] =
                *(const float4*)&hprev[(btile * BT0 + bl) * Hsz + kk];
        }
    __syncthreads();

    const int tb = tid >> 3, tj = tid & 7;
    const int b = btile * BT0 + tb;
    const int j = jtile * 8 + tj;

    u64 xacc[3] = {};
    {
        const u64* xp = (const u64*)&x_s[tb * STRIDE_X];
        const u64* wip[3];
        #pragma unroll
        for (int g = 0; g < 3; g++) wip[g] = (const u64*)&wi_s[(g * 8 + tj) * STRIDE_X];
        #pragma unroll 4
        for (int k2 = 0; k2 < Hsz; k2 += 2) {   // K=512 -> 256 u64
            u64 x0 = xp[k2], x1 = xp[k2 + 1];
            #pragma unroll
            for (int g = 0; g < 3; g++) {
                xacc[g] = ffma2(x0, wip[g][k2],     xacc[g]);
                xacc[g] = ffma2(x1, wip[g][k2 + 1], xacc[g]);
            }
        }
    }

    float gh[3] = {};
    if (!first) {
        u64 acc[3] = {};
        const u64* hp = (const u64*)&h_s[tb * STRIDE_H];
        const u64* wp[3];
        #pragma unroll
        for (int g = 0; g < 3; g++) wp[g] = (const u64*)&w_s[(g * 8 + tj) * STRIDE_H];
        #pragma unroll 4
        for (int k2 = 0; k2 < Hsz / 2; k2 += 2) {
            u64 h0 = hp[k2], h1 = hp[k2 + 1];
            #pragma unroll
            for (int g = 0; g < 3; g++) {
                acc[g] = ffma2(h0, wp[g][k2],     acc[g]);
                acc[g] = ffma2(h1, wp[g][k2 + 1], acc[g]);
            }
        }
        #pragma unroll
        for (int g = 0; g < 3; g++) gh[g] = f2sum(acc[g]);
    }

    float xr = f2sum(xacc[0]) + bih[0 * Hsz + j];
    float xz = f2sum(xacc[1]) + bih[1 * Hsz + j];
    float xn = f2sum(xacc[2]) + bih[2 * Hsz + j];

    float r = sigm(xr + gh[0] + bhh[0 * Hsz + j]);
    float z = sigm(xz + gh[1] + bhh[1 * Hsz + j]);
    float n = tanhf(xn + r * (gh[2] + bhh[2 * Hsz + j]));
    float hpv = first ? 0.0f : h_s[tb * STRIDE_H + j];
    float hv = (1.0f - z) * n + z * hpv;

    float* hnext = bwd ? g_h2b : ((t == Tsz - 1) ? g_h2f : g_hb1[(t & 1) ^ 1]);
    hnext[b * Hsz + j] = hv;
}

// ------------------------------- head -------------------------------------
__global__ void gru_head(const float* __restrict__ W_out,  // [3][256]
                         const float* __restrict__ b_out,  // [3]
                         float* __restrict__ out)          // [256][3]
{
    int b = threadIdx.x;  // 256 threads, 1 block
    float acc0 = b_out[0], acc1 = b_out[1], acc2 = b_out[2];
    for (int k = 0; k < Hsz; k++) {
        float v = g_h2f[b * Hsz + k] + g_h2b[b * Hsz + k];
        acc0 += v * W_out[0 * Hsz + k];
        acc1 += v * W_out[1 * Hsz + k];
        acc2 += v * W_out[2 * Hsz + k];
    }
    float m = fmaxf(acc0, fmaxf(acc1, acc2));
    float e0 = expf(acc0 - m), e1 = expf(acc1 - m), e2 = expf(acc2 - m);
    float inv = 1.0f / (e0 + e1 + e2);
    out[b * 3 + 0] = e0 * inv;
    out[b * 3 + 1] = e1 * inv;
    out[b * 3 + 2] = e2 * inv;
}

// ---------------------------------------------------------------------------
extern "C" void kernel_launch(void* const* d_in, const int* in_sizes, int n_in,
                              void* d_out, int out_size)
{
    const float* x     = (const float*)d_in[0];
    const float* Wih0  = (const float*)d_in[1];
    const float* Whh0  = (const float*)d_in[2];
    const float* bih0  = (const float*)d_in[3];
    const float* bhh0  = (const float*)d_in[4];
    const float* Wih1  = (const float*)d_in[5];
    const float* Whh1  = (const float*)d_in[6];
    const float* bih1  = (const float*)d_in[7];
    const float* bhh1  = (const float*)d_in[8];
    const float* W_out = (const float*)d_in[9];
    const float* b_out = (const float*)d_in[10];
    float* out = (float*)d_out;

    const size_t sm0 = (size_t)(BT0 + ROWS0) * STRIDE_H * sizeof(float);                 // 83,200 B
    const size_t sm1 = (size_t)((BT0 + ROWS1) * STRIDE_H + (BT0 + ROWS1) * STRIDE_X)
                       * sizeof(float);                                                  // 173,824 B
    cudaFuncSetAttribute(gru_step0, cudaFuncAttributeMaxDynamicSharedMemorySize, (int)sm0);
    cudaFuncSetAttribute(gru_step1, cudaFuncAttributeMaxDynamicSharedMemorySize, (int)sm1);

    for (int s = 0; s < Tsz; s++)
        gru_step0<<<dim3(8, 16, 2), 256, sm0>>>(x, Wih0, Whh0, bih0, bhh0, s, s == 0);

    for (int t = 0; t < Tsz; t++)
        gru_step1<<<dim3(8, 32), 256, sm1>>>(Wih1, Whh1, bih1, bhh1, t, t == 0, 0);

    // single backward step of layer 1 (reverse scan at t=T-1 starts from h=0)
    gru_step1<<<dim3(8, 32), 256, sm1>>>(Wih1, Whh1, bih1, bhh1, Tsz - 1, 1, 1);

    gru_head<<<1, 256>>>(W_out, b_out, out);
}

// round 4
// speedup vs baseline: 1.0027x; 1.0027x over previous
#include <cuda_runtime.h>
#include <math.h>

#define Bsz 256
#define Tsz 256
#define Hsz 256
#define G3  768
#define BT0 32
#define ROWS0 48
#define ROWS1 24
#define STRIDE_H 260
#define STRIDE_X 516

__device__ float g_h1[(size_t)Bsz * Tsz * 2 * Hsz];   // layer-0 output [B][T][2H]
__device__ float g_hb0[2][2][Bsz * Hsz];              // layer-0 ping-pong per dir
__device__ float g_hb1[2][Bsz * Hsz];                 // layer-1 fwd ping-pong
__device__ float g_h2f[Bsz * Hsz];
__device__ float g_h2b[Bsz * Hsz];

typedef unsigned long long u64;

__device__ __forceinline__ u64 ffma2(u64 a, u64 b, u64 c) {
    u64 d;
    asm("fma.rn.f32x2 %0, %1, %2, %3;" : "=l"(d) : "l"(a), "l"(b), "l"(c));
    return d;
}
__device__ __forceinline__ float f2sum(u64 a) {
    return __uint_as_float((unsigned)(a & 0xffffffffull)) +
           __uint_as_float((unsigned)(a >> 32));
}
__device__ __forceinline__ float sigm(float v) { return 1.0f / (1.0f + expf(-v)); }

// --------------------------- layer 0 step ---------------------------------
// grid = (8 btiles, 16 jtiles, 2 dirs), block = 256
__global__ void __launch_bounds__(256, 2) gru_step0(
    const float* __restrict__ x,     // [B][T][4]
    const float* __restrict__ Wih0,  // [2][768][4]
    const float* __restrict__ Whh0,  // [2][768][256]
    const float* __restrict__ bih0,  // [2][768]
    const float* __restrict__ bhh0,  // [2][768]
    int s, int first)
{
    extern __shared__ float sm[];
    float* h_s = sm;                   // 32 x 260
    float* w_s = sm + BT0 * STRIDE_H;  // 48 x 260

    const int dir = blockIdx.z;
    const int t   = dir ? (Tsz - 1 - s) : s;
    const int btile = blockIdx.x, jtile = blockIdx.y, tid = threadIdx.x;
    const float* Whh = Whh0 + (size_t)dir * G3 * Hsz;

    for (int i = tid; i < ROWS0 * 64; i += 256) {
        int row = i >> 6, kk = (i & 63) << 2;
        int g = row >> 4, rj = row & 15;
        *(float4*)&w_s[row * STRIDE_H + kk] =
            *(const float4*)&Whh[(size_t)(g * Hsz + jtile * 16 + rj) * Hsz + kk];
    }
    const float* hprev = g_hb0[dir][s & 1];
    if (!first)
        for (int i = tid; i < BT0 * 64; i += 256) {
            int bl = i >> 6, kk = (i & 63) << 2;
            *(float4*)&h_s[bl * STRIDE_H + kk] =
                *(const float4*)&hprev[(btile * BT0 + bl) * Hsz + kk];
        }
    __syncthreads();

    const int tb = tid >> 3, tj = tid & 7;
    const int b = btile * BT0 + tb;

    float gh[3][2] = {};
    if (!first) {
        u64 acc[3][2] = {};
        const u64* hp = (const u64*)&h_s[tb * STRIDE_H];
        const u64* wp[3][2];
        #pragma unroll
        for (int g = 0; g < 3; g++)
            #pragma unroll
            for (int q = 0; q < 2; q++)
                wp[g][q] = (const u64*)&w_s[(g * 16 + q * 8 + tj) * STRIDE_H];
        #pragma unroll 4
        for (int k2 = 0; k2 < Hsz / 2; k2 += 2) {
            u64 h0 = hp[k2], h1 = hp[k2 + 1];
            #pragma unroll
            for (int g = 0; g < 3; g++)
                #pragma unroll
                for (int q = 0; q < 2; q++) {
                    acc[g][q] = ffma2(h0, wp[g][q][k2],     acc[g][q]);
                    acc[g][q] = ffma2(h1, wp[g][q][k2 + 1], acc[g][q]);
                }
        }
        #pragma unroll
        for (int g = 0; g < 3; g++)
            #pragma unroll
            for (int q = 0; q < 2; q++) gh[g][q] = f2sum(acc[g][q]);
    }

    const float4 xv = *(const float4*)&x[((size_t)b * Tsz + t) * 4];
    float* hnext = g_hb0[dir][(s & 1) ^ 1];

    #pragma unroll
    for (int q = 0; q < 2; q++) {
        int j = jtile * 16 + q * 8 + tj;
        const float4 wr = *(const float4*)&Wih0[((size_t)dir * G3 + 0 * Hsz + j) * 4];
        const float4 wz = *(const float4*)&Wih0[((size_t)dir * G3 + 1 * Hsz + j) * 4];
        const float4 wn = *(const float4*)&Wih0[((size_t)dir * G3 + 2 * Hsz + j) * 4];
        float xr = bih0[dir * G3 + 0 * Hsz + j] + xv.x * wr.x + xv.y * wr.y + xv.z * wr.z + xv.w * wr.w;
        float xz = bih0[dir * G3 + 1 * Hsz + j] + xv.x * wz.x + xv.y * wz.y + xv.z * wz.z + xv.w * wz.w;
        float xn = bih0[dir * G3 + 2 * Hsz + j] + xv.x * wn.x + xv.y * wn.y + xv.z * wn.z + xv.w * wn.w;

        float r = sigm(xr + gh[0][q] + bhh0[dir * G3 + 0 * Hsz + j]);
        float z = sigm(xz + gh[1][q] + bhh0[dir * G3 + 1 * Hsz + j]);
        float n = tanhf(xn + r * (gh[2][q] + bhh0[dir * G3 + 2 * Hsz + j]));
        float hpv = first ? 0.0f : h_s[tb * STRIDE_H + j];
        float hv = (1.0f - z) * n + z * hpv;

        hnext[b * Hsz + j] = hv;
        g_h1[((size_t)b * Tsz + t) * (2 * Hsz) + dir * Hsz + j] = hv;
    }
}

// --------------------------- layer 1 step ---------------------------------
// grid = (8 btiles, 32 jtiles), block = 256. bwd=1,first=1 -> single reverse step.
__global__ void __launch_bounds__(256, 1) gru_step1(
    const float* __restrict__ Wih1,  // [2][768][512]
    const float* __restrict__ Whh1,  // [2][768][256]
    const float* __restrict__ bih1,
    const float* __restrict__ bhh1,
    int t, int first, int bwd)
{
    extern __shared__ float sm[];
    float* h_s  = sm;                       // 32 x 260
    float* x_s  = sm + BT0 * STRIDE_H;      // 32 x 516
    float* w_s  = x_s + BT0 * STRIDE_X;     // 24 x 260
    float* wi_s = w_s + ROWS1 * STRIDE_H;   // 24 x 516

    const int btile = blockIdx.x, jtile = blockIdx.y, tid = threadIdx.x;
    const float* Wih = Wih1 + (size_t)bwd * G3 * (2 * Hsz);
    const float* Whh = Whh1 + (size_t)bwd * G3 * Hsz;
    const float* bih = bih1 + bwd * G3;
    const float* bhh = bhh1 + bwd * G3;

    for (int i = tid; i < ROWS1 * 64; i += 256) {
        int row = i >> 6, kk = (i & 63) << 2;
        int g = row >> 3, rj = row & 7;
        *(float4*)&w_s[row * STRIDE_H + kk] =
            *(const float4*)&Whh[(size_t)(g * Hsz + jtile * 8 + rj) * Hsz + kk];
    }
    for (int i = tid; i < ROWS1 * 128; i += 256) {
        int row = i >> 7, kk = (i & 127) << 2;
        int g = row >> 3, rj = row & 7;
        *(float4*)&wi_s[row * STRIDE_X + kk] =
            *(const float4*)&Wih[(size_t)(g * Hsz + jtile * 8 + rj) * (2 * Hsz) + kk];
    }
    for (int i = tid; i < BT0 * 128; i += 256) {
        int bl = i >> 7, kk = (i & 127) << 2;
        *(float4*)&x_s[bl * STRIDE_X + kk] =
            *(const float4*)&g_h1[((size_t)(btile * BT0 + bl) * Tsz + t) * (2 * Hsz) + kk];
    }
    const float* hprev = g_hb1[t & 1];
    if (!first)
        for (int i = tid; i < BT0 * 64; i += 256) {
            int bl = i >> 6, kk = (i & 63) << 2;
            *(float4*)&h_s[bl * STRIDE_H + kk] =
                *(const float4*)&hprev[(btile * BT0 + bl) * Hsz + kk];
        }
    __syncthreads();

    const int tb = tid >> 3, tj = tid & 7;
    const int b = btile * BT0 + tb;
    const int j = jtile * 8 + tj;

    u64 xacc[3] = {};
    {
        const u64* xp = (const u64*)&x_s[tb * STRIDE_X];
        const u64* wip[3];
        #pragma unroll
        for (int g = 0; g < 3; g++) wip[g] = (const u64*)&wi_s[(g * 8 + tj) * STRIDE_X];
        #pragma unroll 4
        for (int k2 = 0; k2 < Hsz; k2 += 2) {   // K=512 -> 256 u64
            u64 x0 = xp[k2], x1 = xp[k2 + 1];
            #pragma unroll
            for (int g = 0; g < 3; g++) {
                xacc[g] = ffma2(x0, wip[g][k2],     xacc[g]);
                xacc[g] = ffma2(x1, wip[g][k2 + 1], xacc[g]);
            }
        }
    }

    float gh[3] = {};
    if (!first) {
        u64 acc[3] = {};
        const u64* hp = (const u64*)&h_s[tb * STRIDE_H];
        const u64* wp[3];
        #pragma unroll
        for (int g = 0; g < 3; g++) wp[g] = (const u64*)&w_s[(g * 8 + tj) * STRIDE_H];
        #pragma unroll 4
        for (int k2 = 0; k2 < Hsz / 2; k2 += 2) {
            u64 h0 = hp[k2], h1 = hp[k2 + 1];
            #pragma unroll
            for (int g = 0; g < 3; g++) {
                acc[g] = ffma2(h0, wp[g][k2],     acc[g]);
                acc[g] = ffma2(h1, wp[g][k2 + 1], acc[g]);
            }
        }
        #pragma unroll
        for (int g = 0; g < 3; g++) gh[g] = f2sum(acc[g]);
    }

    float xr = f2sum(xacc[0]) + bih[0 * Hsz + j];
    float xz = f2sum(xacc[1]) + bih[1 * Hsz + j];
    float xn = f2sum(xacc[2]) + bih[2 * Hsz + j];

    float r = sigm(xr + gh[0] + bhh[0 * Hsz + j]);
    float z = sigm(xz + gh[1] + bhh[1 * Hsz + j]);
    float n = tanhf(xn + r * (gh[2] + bhh[2 * Hsz + j]));
    float hpv = first ? 0.0f : h_s[tb * STRIDE_H + j];
    float hv = (1.0f - z) * n + z * hpv;

    float* hnext = bwd ? g_h2b : ((t == Tsz - 1) ? g_h2f : g_hb1[(t & 1) ^ 1]);
    hnext[b * Hsz + j] = hv;
}

// ------------------------------- head -------------------------------------
__global__ void gru_head(const float* __restrict__ W_out,  // [3][256]
                         const float* __restrict__ b_out,  // [3]
                         float* __restrict__ out)          // [256][3]
{
    int b = threadIdx.x;  // 256 threads, 1 block
    float acc0 = b_out[0], acc1 = b_out[1], acc2 = b_out[2];
    for (int k = 0; k < Hsz; k++) {
        float v = g_h2f[b * Hsz + k] + g_h2b[b * Hsz + k];
        acc0 += v * W_out[0 * Hsz + k];
        acc1 += v * W_out[1 * Hsz + k];
        acc2 += v * W_out[2 * Hsz + k];
    }
    float m = fmaxf(acc0, fmaxf(acc1, acc2));
    float e0 = expf(acc0 - m), e1 = expf(acc1 - m), e2 = expf(acc2 - m);
    float inv = 1.0f / (e0 + e1 + e2);
    out[b * 3 + 0] = e0 * inv;
    out[b * 3 + 1] = e1 * inv;
    out[b * 3 + 2] = e2 * inv;
}

// ---------------------------------------------------------------------------
extern "C" void kernel_launch(void* const* d_in, const int* in_sizes, int n_in,
                              void* d_out, int out_size)
{
    const float* x     = (const float*)d_in[0];
    const float* Wih0  = (const float*)d_in[1];
    const float* Whh0  = (const float*)d_in[2];
    const float* bih0  = (const float*)d_in[3];
    const float* bhh0  = (const float*)d_in[4];
    const float* Wih1  = (const float*)d_in[5];
    const float* Whh1  = (const float*)d_in[6];
    const float* bih1  = (const float*)d_in[7];
    const float* bhh1  = (const float*)d_in[8];
    const float* W_out = (const float*)d_in[9];
    const float* b_out = (const float*)d_in[10];
    float* out = (float*)d_out;

    const size_t sm0 = (size_t)(BT0 + ROWS0) * STRIDE_H * sizeof(float);                 // 83,200 B
    const size_t sm1 = (size_t)((BT0 + ROWS1) * STRIDE_H + (BT0 + ROWS1) * STRIDE_X)
                       * sizeof(float);                                                  // 173,824 B
    cudaFuncSetAttribute(gru_step0, cudaFuncAttributeMaxDynamicSharedMemorySize, (int)sm0);
    cudaFuncSetAttribute(gru_step1, cudaFuncAttributeMaxDynamicSharedMemorySize, (int)sm1);

    for (int s = 0; s < Tsz; s++)
        gru_step0<<<dim3(8, 16, 2), 256, sm0>>>(x, Wih0, Whh0, bih0, bhh0, s, s == 0);

    for (int t = 0; t < Tsz; t++)
        gru_step1<<<dim3(8, 32), 256, sm1>>>(Wih1, Whh1, bih1, bhh1, t, t == 0, 0);

    // single backward step of layer 1 (reverse scan at t=T-1 starts from h=0)
    gru_step1<<<dim3(8, 32), 256, sm1>>>(Wih1, Whh1, bih1, bhh1, Tsz - 1, 1, 1);

    gru_head<<<1, 256>>>(W_out, b_out, out);
}

// round 5
// speedup vs baseline: 1.0037x; 1.0009x over previous
#include <cuda_runtime.h>
#include <math.h>

#define Bsz 256
#define Tsz 256
#define Hsz 256
#define G3  768
#define BT0 32
#define ROWS0 48
#define ROWS1 24
#define STRIDE_H 260
#define STRIDE_X 516

__device__ float g_h1[(size_t)Bsz * Tsz * 2 * Hsz];   // layer-0 output [B][T][2H]
__device__ float g_hb0[2][2][Bsz * Hsz];              // layer-0 ping-pong per dir
__device__ float g_hb1[2][Bsz * Hsz];                 // layer-1 fwd ping-pong
__device__ float g_h2f[Bsz * Hsz];
__device__ float g_h2b[Bsz * Hsz];

typedef unsigned long long u64;

__device__ __forceinline__ u64 ffma2(u64 a, u64 b, u64 c) {
    u64 d;
    asm("fma.rn.f32x2 %0, %1, %2, %3;" : "=l"(d) : "l"(a), "l"(b), "l"(c));
    return d;
}
__device__ __forceinline__ float f2sum(u64 a) {
    return __uint_as_float((unsigned)(a & 0xffffffffull)) +
           __uint_as_float((unsigned)(a >> 32));
}
__device__ __forceinline__ float sigm(float v) { return 1.0f / (1.0f + expf(-v)); }

// --------------------------- layer 0 step ---------------------------------
// grid = (8 btiles, 16 jtiles, 2 dirs), block = 256
__global__ void __launch_bounds__(256, 2) gru_step0(
    const float* __restrict__ x,     // [B][T][4]
    const float* __restrict__ Wih0,  // [2][768][4]
    const float* __restrict__ Whh0,  // [2][768][256]
    const float* __restrict__ bih0,  // [2][768]
    const float* __restrict__ bhh0,  // [2][768]
    int s, int first)
{
    extern __shared__ float sm[];
    float* h_s = sm;                   // 32 x 260
    float* w_s = sm + BT0 * STRIDE_H;  // 48 x 260

    const int dir = blockIdx.z;
    const int t   = dir ? (Tsz - 1 - s) : s;
    const int btile = blockIdx.x, jtile = blockIdx.y, tid = threadIdx.x;
    const float* Whh = Whh0 + (size_t)dir * G3 * Hsz;

    for (int i = tid; i < ROWS0 * 64; i += 256) {
        int row = i >> 6, kk = (i & 63) << 2;
        int g = row >> 4, rj = row & 15;
        *(float4*)&w_s[row * STRIDE_H + kk] =
            *(const float4*)&Whh[(size_t)(g * Hsz + jtile * 16 + rj) * Hsz + kk];
    }
    const float* hprev = g_hb0[dir][s & 1];
    if (!first)
        for (int i = tid; i < BT0 * 64; i += 256) {
            int bl = i >> 6, kk = (i & 63) << 2;
            *(float4*)&h_s[bl * STRIDE_H + kk] =
                *(const float4*)&hprev[(btile * BT0 + bl) * Hsz + kk];
        }
    __syncthreads();

    const int tb = tid >> 3, tj = tid & 7;
    const int b = btile * BT0 + tb;

    float gh[3][2] = {};
    if (!first) {
        u64 acc[3][2] = {};
        const u64* hp = (const u64*)&h_s[tb * STRIDE_H];
        const u64* wp[3][2];
        #pragma unroll
        for (int g = 0; g < 3; g++)
            #pragma unroll
            for (int q = 0; q < 2; q++)
                wp[g][q] = (const u64*)&w_s[(g * 16 + q * 8 + tj) * STRIDE_H];
        #pragma unroll 4
        for (int k2 = 0; k2 < Hsz / 2; k2 += 2) {
            u64 h0 = hp[k2], h1 = hp[k2 + 1];
            #pragma unroll
            for (int g = 0; g < 3; g++)
                #pragma unroll
                for (int q = 0; q < 2; q++) {
                    acc[g][q] = ffma2(h0, wp[g][q][k2],     acc[g][q]);
                    acc[g][q] = ffma2(h1, wp[g][q][k2 + 1], acc[g][q]);
                }
        }
        #pragma unroll
        for (int g = 0; g < 3; g++)
            #pragma unroll
            for (int q = 0; q < 2; q++) gh[g][q] = f2sum(acc[g][q]);
    }

    const float4 xv = *(const float4*)&x[((size_t)b * Tsz + t) * 4];
    float* hnext = g_hb0[dir][(s & 1) ^ 1];

    #pragma unroll
    for (int q = 0; q < 2; q++) {
        int j = jtile * 16 + q * 8 + tj;
        const float4 wr = *(const float4*)&Wih0[((size_t)dir * G3 + 0 * Hsz + j) * 4];
        const float4 wz = *(const float4*)&Wih0[((size_t)dir * G3 + 1 * Hsz + j) * 4];
        const float4 wn = *(const float4*)&Wih0[((size_t)dir * G3 + 2 * Hsz + j) * 4];
        float xr = bih0[dir * G3 + 0 * Hsz + j] + xv.x * wr.x + xv.y * wr.y + xv.z * wr.z + xv.w * wr.w;
        float xz = bih0[dir * G3 + 1 * Hsz + j] + xv.x * wz.x + xv.y * wz.y + xv.z * wz.z + xv.w * wz.w;
        float xn = bih0[dir * G3 + 2 * Hsz + j] + xv.x * wn.x + xv.y * wn.y + xv.z * wn.z + xv.w * wn.w;

        float r = sigm(xr + gh[0][q] + bhh0[dir * G3 + 0 * Hsz + j]);
        float z = sigm(xz + gh[1][q] + bhh0[dir * G3 + 1 * Hsz + j]);
        float n = tanhf(xn + r * (gh[2][q] + bhh0[dir * G3 + 2 * Hsz + j]));
        float hpv = first ? 0.0f : h_s[tb * STRIDE_H + j];
        float hv = (1.0f - z) * n + z * hpv;

        hnext[b * Hsz + j] = hv;
        g_h1[((size_t)b * Tsz + t) * (2 * Hsz) + dir * Hsz + j] = hv;
    }
}

// --------------------------- layer 1 step ---------------------------------
// grid = (8 btiles, 32 jtiles), block = 256. bwd=1,first=1 -> single reverse step.
__global__ void __launch_bounds__(256, 1) gru_step1(
    const float* __restrict__ Wih1,  // [2][768][512]
    const float* __restrict__ Whh1,  // [2][768][256]
    const float* __restrict__ bih1,
    const float* __restrict__ bhh1,
    int t, int first, int bwd)
{
    extern __shared__ float sm[];
    float* h_s  = sm;                       // 32 x 260
    float* x_s  = sm + BT0 * STRIDE_H;      // 32 x 516
    float* w_s  = x_s + BT0 * STRIDE_X;     // 24 x 260
    float* wi_s = w_s + ROWS1 * STRIDE_H;   // 24 x 516

    const int btile = blockIdx.x, jtile = blockIdx.y, tid = threadIdx.x;
    const float* Wih = Wih1 + (size_t)bwd * G3 * (2 * Hsz);
    const float* Whh = Whh1 + (size_t)bwd * G3 * Hsz;
    const float* bih = bih1 + bwd * G3;
    const float* bhh = bhh1 + bwd * G3;

    for (int i = tid; i < ROWS1 * 64; i += 256) {
        int row = i >> 6, kk = (i & 63) << 2;
        int g = row >> 3, rj = row & 7;
        *(float4*)&w_s[row * STRIDE_H + kk] =
            *(const float4*)&Whh[(size_t)(g * Hsz + jtile * 8 + rj) * Hsz + kk];
    }
    for (int i = tid; i < ROWS1 * 128; i += 256) {
        int row = i >> 7, kk = (i & 127) << 2;
        int g = row >> 3, rj = row & 7;
        *(float4*)&wi_s[row * STRIDE_X + kk] =
            *(const float4*)&Wih[(size_t)(g * Hsz + jtile * 8 + rj) * (2 * Hsz) + kk];
    }
    for (int i = tid; i < BT0 * 128; i += 256) {
        int bl = i >> 7, kk = (i & 127) << 2;
        *(float4*)&x_s[bl * STRIDE_X + kk] =
            *(const float4*)&g_h1[((size_t)(btile * BT0 + bl) * Tsz + t) * (2 * Hsz) + kk];
    }
    const float* hprev = g_hb1[t & 1];
    if (!first)
        for (int i = tid; i < BT0 * 64; i += 256) {
            int bl = i >> 6, kk = (i & 63) << 2;
            *(float4*)&h_s[bl * STRIDE_H + kk] =
                *(const float4*)&hprev[(btile * BT0 + bl) * Hsz + kk];
        }
    __syncthreads();

    const int tb = tid >> 3, tj = tid & 7;
    const int b = btile * BT0 + tb;
    const int j = jtile * 8 + tj;

    u64 xacc[3] = {};
    {
        const u64* xp = (const u64*)&x_s[tb * STRIDE_X];
        const u64* wip[3];
        #pragma unroll
        for (int g = 0; g < 3; g++) wip[g] = (const u64*)&wi_s[(g * 8 + tj) * STRIDE_X];
        #pragma unroll 4
        for (int k2 = 0; k2 < Hsz; k2 += 2) {   // K=512 -> 256 u64
            u64 x0 = xp[k2], x1 = xp[k2 + 1];
            #pragma unroll
            for (int g = 0; g < 3; g++) {
                xacc[g] = ffma2(x0, wip[g][k2],     xacc[g]);
                xacc[g] = ffma2(x1, wip[g][k2 + 1], xacc[g]);
            }
        }
    }

    float gh[3] = {};
    if (!first) {
        u64 acc[3] = {};
        const u64* hp = (const u64*)&h_s[tb * STRIDE_H];
        const u64* wp[3];
        #pragma unroll
        for (int g = 0; g < 3; g++) wp[g] = (const u64*)&w_s[(g * 8 + tj) * STRIDE_H];
        #pragma unroll 4
        for (int k2 = 0; k2 < Hsz / 2; k2 += 2) {
            u64 h0 = hp[k2], h1 = hp[k2 + 1];
            #pragma unroll
            for (int g = 0; g < 3; g++) {
                acc[g] = ffma2(h0, wp[g][k2],     acc[g]);
                acc[g] = ffma2(h1, wp[g][k2 + 1], acc[g]);
            }
        }
        #pragma unroll
        for (int g = 0; g < 3; g++) gh[g] = f2sum(acc[g]);
    }

    float xr = f2sum(xacc[0]) + bih[0 * Hsz + j];
    float xz = f2sum(xacc[1]) + bih[1 * Hsz + j];
    float xn = f2sum(xacc[2]) + bih[2 * Hsz + j];

    float r = sigm(xr + gh[0] + bhh[0 * Hsz + j]);
    float z = sigm(xz + gh[1] + bhh[1 * Hsz + j]);
    float n = tanhf(xn + r * (gh[2] + bhh[2 * Hsz + j]));
    float hpv = first ? 0.0f : h_s[tb * STRIDE_H + j];
    float hv = (1.0f - z) * n + z * hpv;

    float* hnext = bwd ? g_h2b : ((t == Tsz - 1) ? g_h2f : g_hb1[(t & 1) ^ 1]);
    hnext[b * Hsz + j] = hv;
}

// ------------------------------- head -------------------------------------
__global__ void gru_head(const float* __restrict__ W_out,  // [3][256]
                         const float* __restrict__ b_out,  // [3]
                         float* __restrict__ out)          // [256][3]
{
    int b = threadIdx.x;  // 256 threads, 1 block
    float acc0 = b_out[0], acc1 = b_out[1], acc2 = b_out[2];
    for (int k = 0; k < Hsz; k++) {
        float v = g_h2f[b * Hsz + k] + g_h2b[b * Hsz + k];
        acc0 += v * W_out[0 * Hsz + k];
        acc1 += v * W_out[1 * Hsz + k];
        acc2 += v * W_out[2 * Hsz + k];
    }
    float m = fmaxf(acc0, fmaxf(acc1, acc2));
    float e0 = expf(acc0 - m), e1 = expf(acc1 - m), e2 = expf(acc2 - m);
    float inv = 1.0f / (e0 + e1 + e2);
    out[b * 3 + 0] = e0 * inv;
    out[b * 3 + 1] = e1 * inv;
    out[b * 3 + 2] = e2 * inv;
}

// ---------------------------------------------------------------------------
extern "C" void kernel_launch(void* const* d_in, const int* in_sizes, int n_in,
                              void* d_out, int out_size)
{
    const float* x     = (const float*)d_in[0];
    const float* Wih0  = (const float*)d_in[1];
    const float* Whh0  = (const float*)d_in[2];
    const float* bih0  = (const float*)d_in[3];
    const float* bhh0  = (const float*)d_in[4];
    const float* Wih1  = (const float*)d_in[5];
    const float* Whh1  = (const float*)d_in[6];
    const float* bih1  = (const float*)d_in[7];
    const float* bhh1  = (const float*)d_in[8];
    const float* W_out = (const float*)d_in[9];
    const float* b_out = (const float*)d_in[10];
    float* out = (float*)d_out;

    const size_t sm0 = (size_t)(BT0 + ROWS0) * STRIDE_H * sizeof(float);                 // 83,200 B
    const size_t sm1 = (size_t)((BT0 + ROWS1) * STRIDE_H + (BT0 + ROWS1) * STRIDE_X)
                       * sizeof(float);                                                  // 173,824 B
    cudaFuncSetAttribute(gru_step0, cudaFuncAttributeMaxDynamicSharedMemorySize, (int)sm0);
    cudaFuncSetAttribute(gru_step1, cudaFuncAttributeMaxDynamicSharedMemorySize, (int)sm1);

    for (int s = 0; s < Tsz; s++)
        gru_step0<<<dim3(8, 16, 2), 256, sm0>>>(x, Wih0, Whh0, bih0, bhh0, s, s == 0);

    for (int t = 0; t < Tsz; t++)
        gru_step1<<<dim3(8, 32), 256, sm1>>>(Wih1, Whh1, bih1, bhh1, t, t == 0, 0);

    // single backward step of layer 1 (reverse scan at t=T-1 starts from h=0)
    gru_step1<<<dim3(8, 32), 256, sm1>>>(Wih1, Whh1, bih1, bhh1, Tsz - 1, 1, 1);

    gru_head<<<1, 256>>>(W_out, b_out, out);
}

// round 6
// speedup vs baseline: 1.6595x; 1.6534x over previous
#include <cuda_runtime.h>
#include <math.h>

#define Tsz 256
#define Hsz 256
#define G3  768

__device__ float g_h1[(size_t)256*256*512];
__device__ float g_hb0[2][2][256*256];
__device__ float g_hb1[2][256*256];
__device__ float g_h2f[256*256];
__device__ float g_h2b[256*256];
__device__ unsigned g_fl0[128], g_fl1[128], g_ex0, g_ex1;

typedef unsigned long long u64;
__device__ __forceinline__ u64 ffma2(u64 a,u64 b,u64 c){u64 d;asm("fma.rn.f32x2 %0,%1,%2,%3;":"=l"(d):"l"(a),"l"(b),"l"(c));return d;}
__device__ __forceinline__ u64 dup2(float v){u64 d;asm("mov.b64 %0,{%1,%2};":"=l"(d):"f"(v),"f"(v));return d;}
__device__ __forceinline__ float lo2(u64 v){return __uint_as_float((unsigned)v);}
__device__ __forceinline__ float hi2(u64 v){return __uint_as_float((unsigned)(v>>32));}
__device__ __forceinline__ float sigm(float v){return 1.f/(1.f+__expf(-v));}
__device__ __forceinline__ float4 ldcg4(const float4* p){float4 v;
    asm volatile("ld.global.cg.v4.f32 {%0,%1,%2,%3},[%4];":"=f"(v.x),"=f"(v.y),"=f"(v.z),"=f"(v.w):"l"(p));return v;}

__device__ __forceinline__ void gbar(unsigned* fl,int lbid,int nb,unsigned tgt){
    __syncthreads();
    if(threadIdx.x==0){__threadfence();atomicExch(&fl[lbid],tgt);}
    int tid=threadIdx.x;
    for(;;){
        int ok=1;
        if(tid<nb){unsigned v;asm volatile("ld.global.cg.u32 %0,[%1];":"=r"(v):"l"(fl+tid));ok=(v>=tgt);}
        if(__syncthreads_and(ok))break;
    }
}

// ---- layer 0 persistent: 128 blocks = dir(2) x bt(4 of 64b) x jt(16 of 16j)
// block 256 = bq(16, 4 b each) x jq(16). Splatted Whh in smem for all steps.
__global__ void __launch_bounds__(256,1) gru0(
    const float* __restrict__ x,const float* __restrict__ Wih0,
    const float* __restrict__ Whh0,const float* __restrict__ bih0,
    const float* __restrict__ bhh0)
{
    extern __shared__ float sm[];
    u64* w2=(u64*)sm;                 // [48][257] splatted (w,w)
    float* hs=sm+48*257*2;            // [256 k][64 b]
    const int dir=blockIdx.x>>6, lb=blockIdx.x&63;
    const int bt=lb>>4, jt=lb&15, tid=threadIdx.x;
    const int bq=tid>>4, jq=tid&15;

    const float* Whh=Whh0+(size_t)dir*G3*Hsz;
    for(int i=tid;i<48*64;i+=256){
        int r=i>>6,k4=(i&63)<<2,g=r>>4,jj=r&15;
        float4 w=*(const float4*)&Whh[(size_t)(g*Hsz+jt*16+jj)*Hsz+k4];
        u64* d=w2+(size_t)r*257+k4;
        d[0]=dup2(w.x);d[1]=dup2(w.y);d[2]=dup2(w.z);d[3]=dup2(w.w);
    }
    const int j=jt*16+jq;
    const float* Wih=Wih0+(size_t)dir*G3*4;
    const float4 wxr=*(const float4*)&Wih[(0*Hsz+j)*4];
    const float4 wxz=*(const float4*)&Wih[(1*Hsz+j)*4];
    const float4 wxn=*(const float4*)&Wih[(2*Hsz+j)*4];
    const float cr=bih0[dir*G3+j],       br=bhh0[dir*G3+j];
    const float cz=bih0[dir*G3+Hsz+j],   bz=bhh0[dir*G3+Hsz+j];
    const float cn=bih0[dir*G3+2*Hsz+j], bn=bhh0[dir*G3+2*Hsz+j];

    if(jt==0){float4 z4={0,0,0,0};float4* d=(float4*)&g_hb0[dir][0][bt*64*Hsz];
        for(int i=tid;i<64*Hsz/4;i+=256)d[i]=z4;}
    unsigned ph=1;
    gbar(g_fl0+dir*64,lb,64,ph++);

    const u64* wr=w2+(size_t)jq*257;
    const u64* wz=w2+(size_t)(16+jq)*257;
    const u64* wn=w2+(size_t)(32+jq)*257;

    for(int s=0;s<Tsz;s++){
        const int t=dir?255-s:s;
        const float* hp=g_hb0[dir][s&1];
        float* hn_=g_hb0[dir][(s&1)^1];
        for(int i=tid;i<4096;i+=256){      // stage h transposed [k][b]
            int b=i&63,k4=(i>>6)<<2;
            float4 h4=ldcg4((const float4*)&hp[(bt*64+b)*Hsz+k4]);
            hs[(k4+0)*64+b]=h4.x;hs[(k4+1)*64+b]=h4.y;
            hs[(k4+2)*64+b]=h4.z;hs[(k4+3)*64+b]=h4.w;
        }
        __syncthreads();
        u64 ar0=0,ar1=0,az0=0,az1=0,an0=0,an1=0;
        const u64* hu=(const u64*)hs;
        #pragma unroll 8
        for(int k=0;k<Hsz;k++){
            u64 h0=hu[k*32+bq*2],h1=hu[k*32+bq*2+1];
            u64 a=wr[k],b_=wz[k],c=wn[k];
            ar0=ffma2(h0,a,ar0);ar1=ffma2(h1,a,ar1);
            az0=ffma2(h0,b_,az0);az1=ffma2(h1,b_,az1);
            an0=ffma2(h0,c,an0);an1=ffma2(h1,c,an1);
        }
        float gr[4]={lo2(ar0),hi2(ar0),lo2(ar1),hi2(ar1)};
        float gz[4]={lo2(az0),hi2(az0),lo2(az1),hi2(az1)};
        float gn[4]={lo2(an0),hi2(an0),lo2(an1),hi2(an1)};
        #pragma unroll
        for(int bb=0;bb<4;bb++){
            int bg=bt*64+bq*4+bb;
            float4 xv=((const float4*)x)[(size_t)bg*Tsz+t];
            float xr=cr+xv.x*wxr.x+xv.y*wxr.y+xv.z*wxr.z+xv.w*wxr.w;
            float xz=cz+xv.x*wxz.x+xv.y*wxz.y+xv.z*wxz.z+xv.w*wxz.w;
            float xn=cn+xv.x*wxn.x+xv.y*wxn.y+xv.z*wxn.z+xv.w*wxn.w;
            float r=sigm(xr+gr[bb]+br);
            float z=sigm(xz+gz[bb]+bz);
            float n=tanhf(xn+r*(gn[bb]+bn));
            float hv=(1.f-z)*n+z*hs[j*64+bq*4+bb];
            hn_[bg*Hsz+j]=hv;
            g_h1[((size_t)bg*Tsz+t)*512+dir*Hsz+j]=hv;
        }
        gbar(g_fl0+dir*64,lb,64,ph++);
    }
    if(tid==0){unsigned o=atomicAdd(&g_ex0,1u);
        if(o==127u){for(int i=0;i<128;i++)g_fl0[i]=0;g_ex0=0;__threadfence();}}
}

// ---- layer 1 persistent: 128 blocks = bt(8 of 32b) x jt(16 of 16j)
// block 256 = b(32) x jp(8 j-pairs). Weights transposed [g][768][16j] in smem.
// bwd=1: single reverse step (h=0), chunks 0..1 only.
__global__ void __launch_bounds__(256,1) gru1(
    const float* __restrict__ Wih1,const float* __restrict__ Whh1,
    const float* __restrict__ bih1,const float* __restrict__ bhh1,int bwd)
{
    extern __shared__ float sm[];
    float* wt=sm;              // [3][768][16]
    float* xb=sm+3*768*16;     // [32][264]
    const int bt=blockIdx.x>>4, jt=blockIdx.x&15, tid=threadIdx.x;
    const int b=tid>>3, jp=tid&7;
    const float* Wih=Wih1+(size_t)bwd*G3*512;
    const float* Whh=Whh1+(size_t)bwd*G3*Hsz;

    for(int i=tid;i<3*16*128;i+=256){   // x-proj weights k 0..511
        int r=i>>7,k4=(i&127)<<2,g=r>>4,jj=r&15;
        float4 w=*(const float4*)&Wih[(size_t)(g*Hsz+jt*16+jj)*512+k4];
        wt[(size_t)(g*G3+k4+0)*16+jj]=w.x;wt[(size_t)(g*G3+k4+1)*16+jj]=w.y;
        wt[(size_t)(g*G3+k4+2)*16+jj]=w.z;wt[(size_t)(g*G3+k4+3)*16+jj]=w.w;
    }
    for(int i=tid;i<3*16*64;i+=256){    // recurrence weights k 512..767
        int r=i>>6,k4=(i&63)<<2,g=r>>4,jj=r&15;
        float4 w=*(const float4*)&Whh[(size_t)(g*Hsz+jt*16+jj)*Hsz+k4];
        wt[(size_t)(g*G3+512+k4+0)*16+jj]=w.x;wt[(size_t)(g*G3+512+k4+1)*16+jj]=w.y;
        wt[(size_t)(g*G3+512+k4+2)*16+jj]=w.z;wt[(size_t)(g*G3+512+k4+3)*16+jj]=w.w;
    }
    const int j0=jt*16+2*jp;
    const float* bi=bih1+bwd*G3; const float* bh=bhh1+bwd*G3;
    const float br0=bi[j0]+bh[j0],           br1=bi[j0+1]+bh[j0+1];
    const float bz0=bi[Hsz+j0]+bh[Hsz+j0],   bz1=bi[Hsz+j0+1]+bh[Hsz+j0+1];
    const float bx0=bi[2*Hsz+j0], bx1=bi[2*Hsz+j0+1];
    const float bn0=bh[2*Hsz+j0], bn1=bh[2*Hsz+j0+1];

    unsigned ph=1;
    if(!bwd){
        if(jt==0){float4 z4={0,0,0,0};float4* d=(float4*)&g_hb1[0][bt*32*Hsz];
            for(int i=tid;i<32*Hsz/4;i+=256)d[i]=z4;}
        gbar(g_fl1,blockIdx.x,128,ph++);
    }
    const u64* wj=(const u64*)wt+jp;
    const int tsteps=bwd?1:Tsz;

    for(int s=0;s<tsteps;s++){
        const int t=bwd?255:s;
        const float* hp=g_hb1[s&1];
        u64 ar=0,az=0,anx=0,anh=0;
        const int cmax=bwd?2:3;
        for(int c=0;c<cmax;c++){
            __syncthreads();
            if(c<2){
                for(int i=tid;i<2048;i+=256){
                    int bl=i>>6,k4=(i&63)<<2;
                    *(float4*)&xb[bl*264+k4]=*(const float4*)
                        &g_h1[((size_t)(bt*32+bl)*Tsz+t)*512+c*256+k4];
                }
            }else{
                for(int i=tid;i<2048;i+=256){
                    int bl=i>>6,k4=(i&63)<<2;
                    *(float4*)&xb[bl*264+k4]=ldcg4((const float4*)&hp[(bt*32+bl)*Hsz+k4]);
                }
            }
            __syncthreads();
            const float* xr_=xb+b*264;
            const u64* w0=wj+(size_t)(0*G3+c*256)*8;
            const u64* w1=wj+(size_t)(1*G3+c*256)*8;
            const u64* w2_=wj+(size_t)(2*G3+c*256)*8;
            u64 an=(c==2)?anh:anx;
            #pragma unroll 8
            for(int k=0;k<256;k++){
                u64 xv=dup2(xr_[k]);
                ar=ffma2(xv,w0[k*8],ar);
                az=ffma2(xv,w1[k*8],az);
                an=ffma2(xv,w2_[k*8],an);
            }
            if(c==2)anh=an;else anx=an;
        }
        float r0=sigm(lo2(ar)+br0), r1=sigm(hi2(ar)+br1);
        float z0=sigm(lo2(az)+bz0), z1=sigm(hi2(az)+bz1);
        float n0=tanhf(lo2(anx)+bx0+r0*(lo2(anh)+bn0));
        float n1=tanhf(hi2(anx)+bx1+r1*(hi2(anh)+bn1));
        float hp0=bwd?0.f:xb[b*264+j0];
        float hp1=bwd?0.f:xb[b*264+j0+1];
        float h0=(1.f-z0)*n0+z0*hp0, h1=(1.f-z1)*n1+z1*hp1;
        float* outp=bwd?g_h2b:((t==255)?g_h2f:g_hb1[(s&1)^1]);
        float2 hv2={h0,h1};
        *(float2*)&outp[(bt*32+b)*Hsz+j0]=hv2;
        if(!bwd)gbar(g_fl1,blockIdx.x,128,ph++);
    }
    if(!bwd&&tid==0){unsigned o=atomicAdd(&g_ex1,1u);
        if(o==127u){for(int i=0;i<128;i++)g_fl1[i]=0;g_ex1=0;__threadfence();}}
}

__global__ void gru_head(const float* __restrict__ W_out,
                         const float* __restrict__ b_out,float* __restrict__ out){
    int b=threadIdx.x;
    float a0=b_out[0],a1=b_out[1],a2=b_out[2];
    for(int k=0;k<Hsz;k++){
        float v=g_h2f[b*Hsz+k]+g_h2b[b*Hsz+k];
        a0+=v*W_out[k];a1+=v*W_out[Hsz+k];a2+=v*W_out[2*Hsz+k];
    }
    float m=fmaxf(a0,fmaxf(a1,a2));
    float e0=expf(a0-m),e1=expf(a1-m),e2=expf(a2-m);
    float inv=1.f/(e0+e1+e2);
    out[b*3+0]=e0*inv;out[b*3+1]=e1*inv;out[b*3+2]=e2*inv;
}

extern "C" void kernel_launch(void* const* d_in,const int* in_sizes,int n_in,
                              void* d_out,int out_size){
    const float* x=(const float*)d_in[0];
    const float* Wih0=(const float*)d_in[1];
    const float* Whh0=(const float*)d_in[2];
    const float* bih0=(const float*)d_in[3];
    const float* bhh0=(const float*)d_in[4];
    const float* Wih1=(const float*)d_in[5];
    const float* Whh1=(const float*)d_in[6];
    const float* bih1=(const float*)d_in[7];
    const float* bhh1=(const float*)d_in[8];
    const float* W_out=(const float*)d_in[9];
    const float* b_out=(const float*)d_in[10];
    float* out=(float*)d_out;

    const int sm0=48*257*8+256*64*4;          // 164,224 B
    const int sm1=(3*768*16+32*264)*4;        // 181,248 B
    cudaFuncSetAttribute(gru0,cudaFuncAttributeMaxDynamicSharedMemorySize,sm0);
    cudaFuncSetAttribute(gru1,cudaFuncAttributeMaxDynamicSharedMemorySize,sm1);

    gru0<<<128,256,sm0>>>(x,Wih0,Whh0,bih0,bhh0);
    gru1<<<128,256,sm1>>>(Wih1,Whh1,bih1,bhh1,0);
    gru1<<<128,256,sm1>>>(Wih1,Whh1,bih1,bhh1,1);
    gru_head<<<1,256>>>(W_out,b_out,out);
}